// round 1
// baseline (speedup 1.0000x reference)
#include <cuda_runtime.h>
#include <cuda_bf16.h>
#include <cstdint>

// Problem constants
#define BB 64
#define DD 256
#define HWN 1024          // 32*32
#define NN 65536          // BB*HWN
#define KK 2048

#define TM 128            // pixels per block tile
#define TN 128            // codes per chunk
#define TKS 8             // k slice

// Scratch (device globals: no allocation allowed)
__device__ float  g_embT[DD * KK];     // [256][2048]
__device__ float  g_sume[KK];
__device__ int    g_idx[NN];
__device__ double g_loss;

// ---------------------------------------------------------------------------
// helpers
// ---------------------------------------------------------------------------
__device__ __forceinline__ unsigned long long pack_dup(float x) {
    unsigned long long r; unsigned int u = __float_as_uint(x);
    asm("mov.b64 %0, {%1, %1};" : "=l"(r) : "r"(u));
    return r;
}
__device__ __forceinline__ void unpack2(unsigned long long v, float& lo, float& hi) {
    asm("mov.b64 {%0, %1}, %2;" : "=f"(lo), "=f"(hi) : "l"(v));
}
__device__ __forceinline__ void fma2(unsigned long long& d,
                                     unsigned long long a, unsigned long long b) {
    asm("fma.rn.f32x2 %0, %1, %2, %0;" : "+l"(d) : "l"(a), "l"(b));
}

// ---------------------------------------------------------------------------
// phase 0a: transpose emb [2048,256] -> g_embT [256,2048]
// ---------------------------------------------------------------------------
__global__ void transpose_kernel(const float* __restrict__ emb) {
    __shared__ float tile[32][33];
    int j0 = blockIdx.x << 5;      // code base  (64 blocks)
    int c0 = blockIdx.y << 5;      // dim base   (8 blocks)
    int tx = threadIdx.x, ty = threadIdx.y;   // 32 x 8
    #pragma unroll
    for (int r = ty; r < 32; r += 8)
        tile[r][tx] = emb[(size_t)(j0 + r) * DD + c0 + tx];
    __syncthreads();
    #pragma unroll
    for (int r = ty; r < 32; r += 8)
        g_embT[(size_t)(c0 + r) * KK + j0 + tx] = tile[tx][r];
}

// ---------------------------------------------------------------------------
// phase 0b: sum(emb^2) per code (sequential, separate roundings) + zero loss
// ---------------------------------------------------------------------------
__global__ void sume_kernel(const float* __restrict__ emb) {
    int j = blockIdx.x * 256 + threadIdx.x;   // 8 blocks x 256
    if (j < KK) {
        const float* e = emb + (size_t)j * DD;
        float s = 0.f;
        for (int c = 0; c < DD; ++c) {
            float v = e[c];
            s = __fadd_rn(s, __fmul_rn(v, v));
        }
        g_sume[j] = s;
    }
    if (j == 0) g_loss = 0.0;
}

// ---------------------------------------------------------------------------
// phase 1: distances + argmin.  One block handles TM=128 pixels vs all 2048
// codes. A tile (128 pixels x 256 dims) resident in smem; B streamed in
// double-buffered 8x128 slices. Per-thread 8x8 microtile via f32x2 FMAs.
// ---------------------------------------------------------------------------
// smem layout (floats):
//   As   [256][128]        @ 0        (32768)
//   Bs   [2][8][128]       @ 32768    (2048)
//   SZ   [128]             @ 34816    (128)
//   RV   [128][17]         @ 34944    (2176)
//   RI   [128][17] (int)   @ 37120    (2176)
#define SMEM_FLOATS 39296
#define SMEM_BYTES  (SMEM_FLOATS * 4)

__global__ void __launch_bounds__(256, 1)
assign_kernel(const float* __restrict__ z) {
    extern __shared__ float sm[];
    float* As  = sm;
    float* Bsm = sm + 32768;
    float* SZ  = sm + 34816;
    float* RV  = sm + 34944;
    int*   RI  = (int*)(sm + 37120);

    const int tid  = threadIdx.x;
    const int warp = tid >> 5, lane = tid & 31;
    const int n0   = blockIdx.x * TM;
    const int b    = n0 >> 10;
    const int hw0  = n0 & 1023;
    const float* zb = z + ((size_t)b << 18) + hw0;   // b * 256 * 1024

    // ---- load A tile: As[c][pix], coalesced per warp-row ----
    #pragma unroll 4
    for (int c = warp; c < DD; c += 8) {
        float4 v = *reinterpret_cast<const float4*>(zb + ((size_t)c << 10) + (lane << 2));
        *reinterpret_cast<float4*>(&As[c * TM + (lane << 2)]) = v;
    }
    __syncthreads();

    // ---- sumz per pixel: sequential, separate-rounded squares ----
    if (tid < TM) {
        float s = 0.f;
        for (int c = 0; c < DD; ++c) {
            float v = As[c * TM + tid];
            s = __fadd_rn(s, __fmul_rn(v, v));
        }
        SZ[tid] = s;
    }

    const int tx = tid & 15;   // code group (8 codes each)
    const int ty = tid >> 4;   // pixel group (8 pixels each)
    const float* a_base = As + (ty << 3);

    float bestv[8];
    int   besti[8];
    #pragma unroll
    for (int i = 0; i < 8; ++i) { bestv[i] = __int_as_float(0x7f800000); besti[i] = 0; }

    for (int jc = 0; jc < KK; jc += TN) {
        unsigned long long acc[4][8];
        #pragma unroll
        for (int pi = 0; pi < 4; ++pi)
            #pragma unroll
            for (int j = 0; j < 8; ++j) acc[pi][j] = 0ULL;

        // preload Bs buffer 0 (k0 = 0)
        {
            int kk = tid >> 5;
            const float* src = g_embT + (size_t)kk * KK + jc + (lane << 2);
            *reinterpret_cast<float4*>(&Bsm[kk * TN + (lane << 2)]) =
                *reinterpret_cast<const float4*>(src);
        }
        __syncthreads();

        #pragma unroll 1
        for (int k0 = 0; k0 < DD; k0 += TKS) {
            const int buf = (k0 >> 3) & 1;
            if (k0 + TKS < DD) {   // prefetch next slice into other buffer
                int kk = tid >> 5;
                const float* src = g_embT + (size_t)(k0 + TKS + kk) * KK + jc + (lane << 2);
                *reinterpret_cast<float4*>(&Bsm[((buf ^ 1) * TKS + kk) * TN + (lane << 2)]) =
                    *reinterpret_cast<const float4*>(src);
            }
            const float* bs = &Bsm[buf * TKS * TN];
            #pragma unroll
            for (int k = 0; k < TKS; ++k) {
                ulonglong2 a01 = *reinterpret_cast<const ulonglong2*>(a_base + (k0 + k) * TM);
                ulonglong2 a23 = *reinterpret_cast<const ulonglong2*>(a_base + (k0 + k) * TM + 4);
                unsigned long long ap[4] = {a01.x, a01.y, a23.x, a23.y};
                float4 b0 = *reinterpret_cast<const float4*>(&bs[k * TN + (tx << 3)]);
                float4 b1 = *reinterpret_cast<const float4*>(&bs[k * TN + (tx << 3) + 4]);
                unsigned long long bp[8];
                bp[0] = pack_dup(b0.x); bp[1] = pack_dup(b0.y);
                bp[2] = pack_dup(b0.z); bp[3] = pack_dup(b0.w);
                bp[4] = pack_dup(b1.x); bp[5] = pack_dup(b1.y);
                bp[6] = pack_dup(b1.z); bp[7] = pack_dup(b1.w);
                #pragma unroll
                for (int pi = 0; pi < 4; ++pi)
                    #pragma unroll
                    for (int j = 0; j < 8; ++j)
                        fma2(acc[pi][j], ap[pi], bp[j]);
            }
            __syncthreads();
        }

        // ---- epilogue: d = fl( fl(sumz+sume) - 2*m ), running argmin ----
        #pragma unroll
        for (int pi = 0; pi < 4; ++pi) {
            const float sz0 = SZ[(ty << 3) + 2 * pi];
            const float sz1 = SZ[(ty << 3) + 2 * pi + 1];
            #pragma unroll
            for (int j = 0; j < 8; ++j) {
                const int code = jc + (tx << 3) + j;
                const float se = g_sume[code];
                float mlo, mhi;
                unpack2(acc[pi][j], mlo, mhi);
                // 2*m is exact => single-rounded fma(-2,m,s1) == jax's s1 - (2*m)
                float d0 = fmaf(mlo, -2.0f, __fadd_rn(sz0, se));
                float d1 = fmaf(mhi, -2.0f, __fadd_rn(sz1, se));
                const int i0 = 2 * pi, i1 = 2 * pi + 1;
                if (d0 < bestv[i0]) { bestv[i0] = d0; besti[i0] = code; }
                if (d1 < bestv[i1]) { bestv[i1] = d1; besti[i1] = code; }
            }
        }
    }

    // ---- cross-thread argmin merge (tie -> lowest index, like jnp.argmin) ----
    #pragma unroll
    for (int i = 0; i < 8; ++i) {
        RV[((ty << 3) + i) * 17 + tx] = bestv[i];
        RI[((ty << 3) + i) * 17 + tx] = besti[i];
    }
    __syncthreads();
    if (tid < TM) {
        float bv = __int_as_float(0x7f800000);
        int   bi = 0x7fffffff;
        #pragma unroll
        for (int t = 0; t < 16; ++t) {
            float v = RV[tid * 17 + t];
            int  id = RI[tid * 17 + t];
            if (v < bv || (v == bv && id < bi)) { bv = v; bi = id; }
        }
        g_idx[n0 + tid] = bi;
    }
}

// ---------------------------------------------------------------------------
// phase 2: gather + straight-through output + loss accumulation
// out[i] = fl( zp + fl(e - zp) ); loss term = fl((e - zp)^2)
// ---------------------------------------------------------------------------
__global__ void __launch_bounds__(256)
quant_kernel(const float* __restrict__ z, const float* __restrict__ emb,
             float* __restrict__ out) {
    const size_t i = ((size_t)blockIdx.x * 256 + threadIdx.x) * 4;
    const int c = (int)((i >> 10) & 255);
    const int n = (int)(((i >> 18) << 10) | (i & 1023));

    int4   id4 = *reinterpret_cast<const int4*>(&g_idx[n]);
    float4 zp  = *reinterpret_cast<const float4*>(&z[i]);

    float e0 = __ldg(&emb[(size_t)id4.x * DD + c]);
    float e1 = __ldg(&emb[(size_t)id4.y * DD + c]);
    float e2 = __ldg(&emb[(size_t)id4.z * DD + c]);
    float e3 = __ldg(&emb[(size_t)id4.w * DD + c]);

    float t0 = __fsub_rn(e0, zp.x);
    float t1 = __fsub_rn(e1, zp.y);
    float t2 = __fsub_rn(e2, zp.z);
    float t3 = __fsub_rn(e3, zp.w);

    float4 o;
    o.x = __fadd_rn(zp.x, t0);
    o.y = __fadd_rn(zp.y, t1);
    o.z = __fadd_rn(zp.z, t2);
    o.w = __fadd_rn(zp.w, t3);
    *reinterpret_cast<float4*>(&out[i]) = o;

    double s = (double)__fmul_rn(t0, t0) + (double)__fmul_rn(t1, t1)
             + (double)__fmul_rn(t2, t2) + (double)__fmul_rn(t3, t3);

    // block reduction -> one atomic per block
    #pragma unroll
    for (int off = 16; off; off >>= 1)
        s += __shfl_down_sync(0xffffffffu, s, off);
    __shared__ double ws[8];
    const int warp = threadIdx.x >> 5, lane = threadIdx.x & 31;
    if (lane == 0) ws[warp] = s;
    __syncthreads();
    if (threadIdx.x == 0) {
        double t = 0.0;
        #pragma unroll
        for (int w = 0; w < 8; ++w) t += ws[w];
        atomicAdd(&g_loss, t);
    }
}

// ---------------------------------------------------------------------------
// phase 3: write idx (as float) and loss per output layout
// ---------------------------------------------------------------------------
__global__ void write_extras_kernel(float* __restrict__ out, int out_size) {
    const int t  = blockIdx.x * 256 + threadIdx.x;
    const int ZQ = NN * DD;          // 16777216
    if (out_size == NN) {            // layout: idx only
        if (t < NN) out[t] = (float)g_idx[t];
        return;
    }
    const int rem = out_size - ZQ;
    if (rem >= NN && t < NN) out[ZQ + t] = (float)g_idx[t];
    if (rem >= NN + 1 && t == 0) {
        float m = (float)(g_loss * (1.0 / 16777216.0));
        out[ZQ + NN] = __fadd_rn(m, __fmul_rn(0.25f, m));   // m + BETA*m
    }
    if (rem >= 2 * NN + 1 && t < NN) out[ZQ + NN + 1 + t] = (float)g_idx[t];
}

// ---------------------------------------------------------------------------
extern "C" void kernel_launch(void* const* d_in, const int* in_sizes, int n_in,
                              void* d_out, int out_size) {
    const float* z;
    const float* emb;
    if (in_sizes[0] == NN * DD) { z = (const float*)d_in[0]; emb = (const float*)d_in[1]; }
    else                        { z = (const float*)d_in[1]; emb = (const float*)d_in[0]; }
    float* out = (float*)d_out;

    cudaFuncSetAttribute(assign_kernel,
                         cudaFuncAttributeMaxDynamicSharedMemorySize, SMEM_BYTES);

    transpose_kernel<<<dim3(64, 8), dim3(32, 8)>>>(emb);
    sume_kernel<<<8, 256>>>(emb);
    assign_kernel<<<NN / TM, 256, SMEM_BYTES>>>(z);
    if (out_size >= NN * DD)
        quant_kernel<<<(NN * DD) / (256 * 4), 256>>>(z, emb, out);
    if (out_size > NN * DD || out_size == NN)
        write_extras_kernel<<<NN / 256, 256>>>(out, out_size);
}

// round 2
// speedup vs baseline: 1.0009x; 1.0009x over previous
#include <cuda_runtime.h>
#include <cuda_bf16.h>
#include <cstdint>

// Problem constants
#define BB 64
#define DD 256
#define HWN 1024          // 32*32
#define NN 65536          // BB*HWN
#define KK 2048

#define TM 128            // pixels per block tile
#define TN 128            // codes per chunk
#define TKS 8             // k slice

// Scratch (device globals: no allocation allowed)
__device__ float  g_embT[DD * KK];     // [256][2048]
__device__ float  g_sume[KK];
__device__ int    g_idx[NN];
__device__ double g_loss;

// ---------------------------------------------------------------------------
// helpers
// ---------------------------------------------------------------------------
__device__ __forceinline__ unsigned long long pack_dup(float x) {
    unsigned long long r; unsigned int u = __float_as_uint(x);
    asm("mov.b64 %0, {%1, %1};" : "=l"(r) : "r"(u));
    return r;
}
__device__ __forceinline__ void unpack2(unsigned long long v, float& lo, float& hi) {
    asm("mov.b64 {%0, %1}, %2;" : "=f"(lo), "=f"(hi) : "l"(v));
}
__device__ __forceinline__ void fma2(unsigned long long& d,
                                     unsigned long long a, unsigned long long b) {
    asm("fma.rn.f32x2 %0, %1, %2, %0;" : "+l"(d) : "l"(a), "l"(b));
}

// ---------------------------------------------------------------------------
// phase 0a: transpose emb [2048,256] -> g_embT [256,2048]
// ---------------------------------------------------------------------------
__global__ void transpose_kernel(const float* __restrict__ emb) {
    __shared__ float tile[32][33];
    int j0 = blockIdx.x << 5;      // code base  (64 blocks)
    int c0 = blockIdx.y << 5;      // dim base   (8 blocks)
    int tx = threadIdx.x, ty = threadIdx.y;   // 32 x 8
    #pragma unroll
    for (int r = ty; r < 32; r += 8)
        tile[r][tx] = emb[(size_t)(j0 + r) * DD + c0 + tx];
    __syncthreads();
    #pragma unroll
    for (int r = ty; r < 32; r += 8)
        g_embT[(size_t)(c0 + r) * KK + j0 + tx] = tile[tx][r];
}

// ---------------------------------------------------------------------------
// phase 0b: sum(emb^2) per code (sequential, separate roundings) + zero loss
// ---------------------------------------------------------------------------
__global__ void sume_kernel(const float* __restrict__ emb) {
    int j = blockIdx.x * 256 + threadIdx.x;   // 8 blocks x 256
    if (j < KK) {
        const float* e = emb + (size_t)j * DD;
        float s = 0.f;
        for (int c = 0; c < DD; ++c) {
            float v = e[c];
            s = __fadd_rn(s, __fmul_rn(v, v));
        }
        g_sume[j] = s;
    }
    if (j == 0) g_loss = 0.0;
}

// ---------------------------------------------------------------------------
// phase 1: distances + argmin.  One block handles TM=128 pixels vs all 2048
// codes. A tile (128 pixels x 256 dims) resident in smem; B streamed in
// double-buffered 8x128 slices. Per-thread 8x8 microtile via f32x2 FMAs.
// ---------------------------------------------------------------------------
// smem layout (floats):
//   As   [256][128]        @ 0        (32768)
//   Bs   [2][8][128]       @ 32768    (2048)
//   SZ   [128]             @ 34816    (128)
//   RV   [128][17]         @ 34944    (2176)
//   RI   [128][17] (int)   @ 37120    (2176)
#define SMEM_FLOATS 39296
#define SMEM_BYTES  (SMEM_FLOATS * 4)

__global__ void __launch_bounds__(256, 1)
assign_kernel(const float* __restrict__ z) {
    extern __shared__ float sm[];
    float* As  = sm;
    float* Bsm = sm + 32768;
    float* SZ  = sm + 34816;
    float* RV  = sm + 34944;
    int*   RI  = (int*)(sm + 37120);

    const int tid  = threadIdx.x;
    const int warp = tid >> 5, lane = tid & 31;
    const int n0   = blockIdx.x * TM;
    const int b    = n0 >> 10;
    const int hw0  = n0 & 1023;
    const float* zb = z + ((size_t)b << 18) + hw0;   // b * 256 * 1024

    // ---- load A tile: As[c][pix], coalesced per warp-row ----
    #pragma unroll 4
    for (int c = warp; c < DD; c += 8) {
        float4 v = *reinterpret_cast<const float4*>(zb + ((size_t)c << 10) + (lane << 2));
        *reinterpret_cast<float4*>(&As[c * TM + (lane << 2)]) = v;
    }
    __syncthreads();

    // ---- sumz per pixel: sequential, separate-rounded squares ----
    if (tid < TM) {
        float s = 0.f;
        for (int c = 0; c < DD; ++c) {
            float v = As[c * TM + tid];
            s = __fadd_rn(s, __fmul_rn(v, v));
        }
        SZ[tid] = s;
    }

    const int tx = tid & 15;   // code group (8 codes each)
    const int ty = tid >> 4;   // pixel group (8 pixels each)
    const float* a_base = As + (ty << 3);

    float bestv[8];
    int   besti[8];
    #pragma unroll
    for (int i = 0; i < 8; ++i) { bestv[i] = __int_as_float(0x7f800000); besti[i] = 0; }

    for (int jc = 0; jc < KK; jc += TN) {
        unsigned long long acc[4][8];
        #pragma unroll
        for (int pi = 0; pi < 4; ++pi)
            #pragma unroll
            for (int j = 0; j < 8; ++j) acc[pi][j] = 0ULL;

        // preload Bs buffer 0 (k0 = 0)
        {
            int kk = tid >> 5;
            const float* src = g_embT + (size_t)kk * KK + jc + (lane << 2);
            *reinterpret_cast<float4*>(&Bsm[kk * TN + (lane << 2)]) =
                *reinterpret_cast<const float4*>(src);
        }
        __syncthreads();

        #pragma unroll 1
        for (int k0 = 0; k0 < DD; k0 += TKS) {
            const int buf = (k0 >> 3) & 1;
            if (k0 + TKS < DD) {   // prefetch next slice into other buffer
                int kk = tid >> 5;
                const float* src = g_embT + (size_t)(k0 + TKS + kk) * KK + jc + (lane << 2);
                *reinterpret_cast<float4*>(&Bsm[((buf ^ 1) * TKS + kk) * TN + (lane << 2)]) =
                    *reinterpret_cast<const float4*>(src);
            }
            const float* bs = &Bsm[buf * TKS * TN];
            #pragma unroll
            for (int k = 0; k < TKS; ++k) {
                ulonglong2 a01 = *reinterpret_cast<const ulonglong2*>(a_base + (k0 + k) * TM);
                ulonglong2 a23 = *reinterpret_cast<const ulonglong2*>(a_base + (k0 + k) * TM + 4);
                unsigned long long ap[4] = {a01.x, a01.y, a23.x, a23.y};
                float4 b0 = *reinterpret_cast<const float4*>(&bs[k * TN + (tx << 3)]);
                float4 b1 = *reinterpret_cast<const float4*>(&bs[k * TN + (tx << 3) + 4]);
                unsigned long long bp[8];
                bp[0] = pack_dup(b0.x); bp[1] = pack_dup(b0.y);
                bp[2] = pack_dup(b0.z); bp[3] = pack_dup(b0.w);
                bp[4] = pack_dup(b1.x); bp[5] = pack_dup(b1.y);
                bp[6] = pack_dup(b1.z); bp[7] = pack_dup(b1.w);
                #pragma unroll
                for (int pi = 0; pi < 4; ++pi)
                    #pragma unroll
                    for (int j = 0; j < 8; ++j)
                        fma2(acc[pi][j], ap[pi], bp[j]);
            }
            __syncthreads();
        }

        // ---- epilogue: d = fl( fl(sumz+sume) - 2*m ), running argmin ----
        #pragma unroll
        for (int pi = 0; pi < 4; ++pi) {
            const float sz0 = SZ[(ty << 3) + 2 * pi];
            const float sz1 = SZ[(ty << 3) + 2 * pi + 1];
            #pragma unroll
            for (int j = 0; j < 8; ++j) {
                const int code = jc + (tx << 3) + j;
                const float se = g_sume[code];
                float mlo, mhi;
                unpack2(acc[pi][j], mlo, mhi);
                // 2*m is exact => single-rounded fma(-2,m,s1) == jax's s1 - (2*m)
                float d0 = fmaf(mlo, -2.0f, __fadd_rn(sz0, se));
                float d1 = fmaf(mhi, -2.0f, __fadd_rn(sz1, se));
                const int i0 = 2 * pi, i1 = 2 * pi + 1;
                if (d0 < bestv[i0]) { bestv[i0] = d0; besti[i0] = code; }
                if (d1 < bestv[i1]) { bestv[i1] = d1; besti[i1] = code; }
            }
        }
    }

    // ---- cross-thread argmin merge (tie -> lowest index, like jnp.argmin) ----
    #pragma unroll
    for (int i = 0; i < 8; ++i) {
        RV[((ty << 3) + i) * 17 + tx] = bestv[i];
        RI[((ty << 3) + i) * 17 + tx] = besti[i];
    }
    __syncthreads();
    if (tid < TM) {
        float bv = __int_as_float(0x7f800000);
        int   bi = 0x7fffffff;
        #pragma unroll
        for (int t = 0; t < 16; ++t) {
            float v = RV[tid * 17 + t];
            int  id = RI[tid * 17 + t];
            if (v < bv || (v == bv && id < bi)) { bv = v; bi = id; }
        }
        g_idx[n0 + tid] = bi;
    }
}

// ---------------------------------------------------------------------------
// phase 2: gather + straight-through output + loss accumulation
// out[i] = fl( zp + fl(e - zp) ); loss term = fl((e - zp)^2)
// ---------------------------------------------------------------------------
__global__ void __launch_bounds__(256)
quant_kernel(const float* __restrict__ z, const float* __restrict__ emb,
             float* __restrict__ out) {
    const size_t i = ((size_t)blockIdx.x * 256 + threadIdx.x) * 4;
    const int c = (int)((i >> 10) & 255);
    const int n = (int)(((i >> 18) << 10) | (i & 1023));

    int4   id4 = *reinterpret_cast<const int4*>(&g_idx[n]);
    float4 zp  = *reinterpret_cast<const float4*>(&z[i]);

    float e0 = __ldg(&emb[(size_t)id4.x * DD + c]);
    float e1 = __ldg(&emb[(size_t)id4.y * DD + c]);
    float e2 = __ldg(&emb[(size_t)id4.z * DD + c]);
    float e3 = __ldg(&emb[(size_t)id4.w * DD + c]);

    float t0 = __fsub_rn(e0, zp.x);
    float t1 = __fsub_rn(e1, zp.y);
    float t2 = __fsub_rn(e2, zp.z);
    float t3 = __fsub_rn(e3, zp.w);

    float4 o;
    o.x = __fadd_rn(zp.x, t0);
    o.y = __fadd_rn(zp.y, t1);
    o.z = __fadd_rn(zp.z, t2);
    o.w = __fadd_rn(zp.w, t3);
    *reinterpret_cast<float4*>(&out[i]) = o;

    double s = (double)__fmul_rn(t0, t0) + (double)__fmul_rn(t1, t1)
             + (double)__fmul_rn(t2, t2) + (double)__fmul_rn(t3, t3);

    // block reduction -> one atomic per block
    #pragma unroll
    for (int off = 16; off; off >>= 1)
        s += __shfl_down_sync(0xffffffffu, s, off);
    __shared__ double ws[8];
    const int warp = threadIdx.x >> 5, lane = threadIdx.x & 31;
    if (lane == 0) ws[warp] = s;
    __syncthreads();
    if (threadIdx.x == 0) {
        double t = 0.0;
        #pragma unroll
        for (int w = 0; w < 8; ++w) t += ws[w];
        atomicAdd(&g_loss, t);
    }
}

// ---------------------------------------------------------------------------
// phase 3: write idx (as float) and loss per output layout
// ---------------------------------------------------------------------------
__global__ void write_extras_kernel(float* __restrict__ out, int out_size) {
    const int t  = blockIdx.x * 256 + threadIdx.x;
    const int ZQ = NN * DD;          // 16777216
    if (out_size == NN) {            // layout: idx only
        if (t < NN) out[t] = (float)g_idx[t];
        return;
    }
    const int rem = out_size - ZQ;
    if (rem >= NN && t < NN) out[ZQ + t] = (float)g_idx[t];
    if (rem >= NN + 1 && t == 0) {
        float m = (float)(g_loss * (1.0 / 16777216.0));
        out[ZQ + NN] = __fadd_rn(m, __fmul_rn(0.25f, m));   // m + BETA*m
    }
    if (rem >= 2 * NN + 1 && t < NN) out[ZQ + NN + 1 + t] = (float)g_idx[t];
}

// ---------------------------------------------------------------------------
extern "C" void kernel_launch(void* const* d_in, const int* in_sizes, int n_in,
                              void* d_out, int out_size) {
    const float* z;
    const float* emb;
    if (in_sizes[0] == NN * DD) { z = (const float*)d_in[0]; emb = (const float*)d_in[1]; }
    else                        { z = (const float*)d_in[1]; emb = (const float*)d_in[0]; }
    float* out = (float*)d_out;

    cudaFuncSetAttribute(assign_kernel,
                         cudaFuncAttributeMaxDynamicSharedMemorySize, SMEM_BYTES);

    transpose_kernel<<<dim3(64, 8), dim3(32, 8)>>>(emb);
    sume_kernel<<<8, 256>>>(emb);
    assign_kernel<<<NN / TM, 256, SMEM_BYTES>>>(z);
    if (out_size >= NN * DD)
        quant_kernel<<<(NN * DD) / (256 * 4), 256>>>(z, emb, out);
    if (out_size > NN * DD || out_size == NN)
        write_extras_kernel<<<NN / 256, 256>>>(out, out_size);
}